// round 1
// baseline (speedup 1.0000x reference)
#include <cuda_runtime.h>
#include <cuda_bf16.h>
#include <math.h>

// Problem constants (fixed-shape problem)
#define NN   40000      // nodes
#define NE   640000     // edges
#define FIN  512
#define HH   128
#define CO   40

// ---------------- scratch (device globals; no allocation allowed) ----------------
__device__ __align__(16) float g_xh [NN*HH];
__device__ __align__(16) float g_tx1[NN*HH];
__device__ __align__(16) float g_s  [NN*HH];
__device__ __align__(16) float g_t1 [NN*HH];
__device__ __align__(16) float g_xc [NN*HH];   // cell input/output chain
__device__ float g_deg   [NN];
__device__ float g_dis   [NN];
__device__ float g_loopw [NN];
__device__ float g_invcnt[NN];   // used as count accumulator, then inverted

// ---------------- graph prep ----------------
__global__ void prep_zero_kernel() {
    int n = blockIdx.x * blockDim.x + threadIdx.x;
    if (n < NN) { g_deg[n] = 0.0f; g_loopw[n] = 1.0f; g_invcnt[n] = 0.0f; }
}

__global__ void prep_edge_kernel(const int* __restrict__ ei, const float* __restrict__ w) {
    int e = blockIdx.x * blockDim.x + threadIdx.x;
    if (e >= NE) return;
    int s = ei[e], d = ei[NE + e];
    float we = w[e];
    if (s != d) {
        atomicAdd(&g_deg[s], we);
        atomicAdd(&g_invcnt[d], 1.0f);
    } else {
        g_loopw[s] = we;   // keep existing self-loop weight
    }
}

__global__ void prep_node_kernel() {
    int n = blockIdx.x * blockDim.x + threadIdx.x;
    if (n >= NN) return;
    float dg = g_deg[n];
    g_dis[n]    = (dg > 0.0f) ? rsqrtf(dg) : 0.0f;
    g_invcnt[n] = 1.0f / (g_invcnt[n] + 1.0f);
}

// ---------------- per-cell init: tx1 = 0 ; s = loop_w * xh ----------------
__global__ void init_ts_kernel(const float4* __restrict__ xh,
                               float4* __restrict__ tx1, float4* __restrict__ s) {
    int i = blockIdx.x * blockDim.x + threadIdx.x;      // over NN*32 float4s
    if (i >= NN * (HH/4)) return;
    int n = i >> 5;                                      // HH/4 = 32 per node
    float lw = g_loopw[n];
    float4 v = xh[i];
    tx1[i] = make_float4(0.f, 0.f, 0.f, 0.f);
    s[i]   = make_float4(v.x*lw, v.y*lw, v.z*lw, v.w*lw);
}

// ---------------- fused edge scatter: warp per edge, lane per float4 ----------------
__global__ __launch_bounds__(256)
void scatter_kernel(const int* __restrict__ ei, const float* __restrict__ w,
                    const float4* __restrict__ xh,
                    float4* __restrict__ tx1, float4* __restrict__ s) {
    int gw   = (blockIdx.x * blockDim.x + threadIdx.x) >> 5;  // edge id
    int lane = threadIdx.x & 31;
    if (gw >= NE) return;
    int src = ei[gw], dst = ei[NE + gw];
    if (src == dst) return;                       // loops: norm=0, we=0
    float we   = w[gw];
    float coef = -g_dis[src] * we * g_dis[dst];   // cheb L_hat off-diag
    float4 v = xh[src * 32 + lane];
    float4 a = make_float4(v.x*coef, v.y*coef, v.z*coef, v.w*coef);
    float4 b = make_float4(v.x*we,   v.y*we,   v.z*we,   v.w*we);
    atomicAdd(&tx1[dst * 32 + lane], a);          // sm_90+ vector RED
    atomicAdd(&s  [dst * 32 + lane], b);
}

// ---------------- generic fp32 GEMM with fused epilogue ----------------
// C[N x M] = epi( A[N x K] @ B[K x M] )
#define F_BIAS       1
#define F_LEAKY      2
#define F_ADDC_PRE   4   // v += C_old before leaky
#define F_ADDC_POST  8   // v = C_old + leaky(v)
#define F_ROWSCALE  16   // v *= rowscale[row] before bias (SAGE mean)

template<int FLAGS>
__global__ __launch_bounds__(256)
void gemm_kernel(const float* __restrict__ A, const float* __restrict__ B,
                 const float* __restrict__ bias, float* __restrict__ C,
                 const float* __restrict__ rowscale, int K, int M) {
    __shared__ float As[32][65];     // padded: conflict-free transposed store
    __shared__ float Bs[32][128];

    const int tid = threadIdx.x;
    const int r0  = blockIdx.x * 64;
    const int c0  = blockIdx.y * 128;
    const int tx  = tid & 15;        // 16 col-groups * 8 cols
    const int ty  = tid >> 4;        // 16 row-groups * 4 rows

    float acc[4][8];
    #pragma unroll
    for (int i = 0; i < 4; i++)
        #pragma unroll
        for (int j = 0; j < 8; j++) acc[i][j] = 0.0f;

    for (int k0 = 0; k0 < K; k0 += 32) {
        // A tile: 64 rows x 32 cols, transposed into As[k][m]
        #pragma unroll
        for (int i = 0; i < 2; i++) {
            int idx = tid + i * 256;          // 0..511
            int row = idx >> 3;
            int kc  = (idx & 7) << 2;
            float4 v = *(const float4*)&A[(size_t)(r0 + row) * K + k0 + kc];
            As[kc+0][row] = v.x; As[kc+1][row] = v.y;
            As[kc+2][row] = v.z; As[kc+3][row] = v.w;
        }
        // B tile: 32 rows x 128 cols
        #pragma unroll
        for (int i = 0; i < 4; i++) {
            int idx = tid + i * 256;          // 0..1023
            int kr  = idx >> 5;
            int col = (idx & 31) << 2;
            float4 v = make_float4(0.f, 0.f, 0.f, 0.f);
            if (c0 + col < M) v = *(const float4*)&B[(size_t)(k0 + kr) * M + c0 + col];
            *(float4*)&Bs[kr][col] = v;
        }
        __syncthreads();

        #pragma unroll
        for (int kk = 0; kk < 32; kk++) {
            float a[4];
            #pragma unroll
            for (int i = 0; i < 4; i++) a[i] = As[kk][ty*4 + i];
            float4 b0 = *(const float4*)&Bs[kk][tx*8];
            float4 b1 = *(const float4*)&Bs[kk][tx*8 + 4];
            float b[8] = {b0.x, b0.y, b0.z, b0.w, b1.x, b1.y, b1.z, b1.w};
            #pragma unroll
            for (int i = 0; i < 4; i++)
                #pragma unroll
                for (int j = 0; j < 8; j++)
                    acc[i][j] += a[i] * b[j];
        }
        __syncthreads();
    }

    // epilogue
    float rs[4];
    #pragma unroll
    for (int i = 0; i < 4; i++)
        rs[i] = (FLAGS & F_ROWSCALE) ? rowscale[r0 + ty*4 + i] : 1.0f;

    #pragma unroll
    for (int i = 0; i < 4; i++) {
        int row = r0 + ty*4 + i;
        #pragma unroll
        for (int j = 0; j < 8; j++) {
            int col = c0 + tx*8 + j;
            if (col >= M) continue;
            size_t off = (size_t)row * M + col;
            float v = acc[i][j] * rs[i];
            if (FLAGS & F_BIAS)      v += bias[col];
            if (FLAGS & F_ADDC_PRE)  v += C[off];
            if (FLAGS & F_LEAKY)     v = (v > 0.0f) ? v : 0.01f * v;
            if (FLAGS & F_ADDC_POST) v += C[off];
            C[off] = v;
        }
    }
}

// ---------------- log_softmax over 40 cols, warp per row ----------------
__global__ __launch_bounds__(256)
void logsoftmax_kernel(float* __restrict__ out) {
    int row  = (blockIdx.x * blockDim.x + threadIdx.x) >> 5;
    int lane = threadIdx.x & 31;
    if (row >= NN) return;
    float* p = out + (size_t)row * CO;
    float v0 = p[lane];
    float v1 = (lane < CO - 32) ? p[32 + lane] : -3.4e38f;
    float m = fmaxf(v0, v1);
    #pragma unroll
    for (int o = 16; o > 0; o >>= 1) m = fmaxf(m, __shfl_xor_sync(0xffffffffu, m, o));
    float e = expf(v0 - m) + ((lane < CO - 32) ? expf(v1 - m) : 0.0f);
    #pragma unroll
    for (int o = 16; o > 0; o >>= 1) e += __shfl_xor_sync(0xffffffffu, e, o);
    float ls = m + logf(e);
    p[lane] = v0 - ls;
    if (lane < CO - 32) p[32 + lane] = v1 - ls;
}

// ---------------- launch ----------------
static void run_cell(const float* x_in, const int* ei, const float* w,
                     const float* pw, const float* pb,
                     const float* cw0, const float* cw1, const float* cb,
                     const float* sw, const float* sb,
                     const float* lw, const float* lb,
                     float* xh, float* tx1, float* s, float* t1, float* x_out,
                     float* invcnt, int Kin) {
    dim3 gg((NN + 63) / 64, 1);
    // 1. xh = x_in @ pw + pb
    gemm_kernel<F_BIAS><<<dim3((NN+63)/64, (HH+127)/128), 256>>>(x_in, pw, pb, xh, nullptr, Kin, HH);
    // 2. tx1 = 0 ; s = loop_w * xh
    init_ts_kernel<<<(NN*(HH/4) + 255)/256, 256>>>((const float4*)xh, (float4*)tx1, (float4*)s);
    // 3. fused scatter
    scatter_kernel<<<(NE*32 + 255)/256, 256>>>(ei, w, (const float4*)xh, (float4*)tx1, (float4*)s);
    // 4. t1 = xh @ cw0 + cb
    gemm_kernel<F_BIAS><<<gg, 256>>>(xh, cw0, cb, t1, nullptr, HH, HH);
    // 5. t1 = leaky(tx1 @ cw1 + t1)
    gemm_kernel<F_ADDC_PRE | F_LEAKY><<<gg, 256>>>(tx1, cw1, nullptr, t1, nullptr, HH, HH);
    // 6. t1 += leaky((s * invcnt_row) @ sw + sb)
    gemm_kernel<F_ROWSCALE | F_BIAS | F_LEAKY | F_ADDC_POST><<<gg, 256>>>(s, sw, sb, t1, invcnt, HH, HH);
    // 7. x_out = t1 @ lw + lb
    gemm_kernel<F_BIAS><<<gg, 256>>>(t1, lw, lb, x_out, nullptr, HH, HH);
}

extern "C" void kernel_launch(void* const* d_in, const int* in_sizes, int n_in,
                              void* d_out, int out_size) {
    const float* x    = (const float*)d_in[0];
    const int*   ei   = (const int*)  d_in[1];
    const float* w    = (const float*)d_in[2];
    const float* pre_w1 = (const float*)d_in[3];
    const float* pre_b1 = (const float*)d_in[4];
    const float* cw0_1  = (const float*)d_in[5];
    const float* cw1_1  = (const float*)d_in[6];
    const float* cb_1   = (const float*)d_in[7];
    const float* sw_1   = (const float*)d_in[8];
    const float* sb_1   = (const float*)d_in[9];
    const float* lw_1   = (const float*)d_in[10];
    const float* lb_1   = (const float*)d_in[11];
    const float* pre_w2 = (const float*)d_in[12];
    const float* pre_b2 = (const float*)d_in[13];
    const float* cw0_2  = (const float*)d_in[14];
    const float* cw1_2  = (const float*)d_in[15];
    const float* cb_2   = (const float*)d_in[16];
    const float* sw_2   = (const float*)d_in[17];
    const float* sb_2   = (const float*)d_in[18];
    const float* lw_2   = (const float*)d_in[19];
    const float* lb_2   = (const float*)d_in[20];
    const float* cls_w  = (const float*)d_in[21];
    const float* cls_b  = (const float*)d_in[22];
    float* out = (float*)d_out;

    void *p_xh, *p_tx1, *p_s, *p_t1, *p_xc, *p_invcnt;
    cudaGetSymbolAddress(&p_xh,  g_xh);
    cudaGetSymbolAddress(&p_tx1, g_tx1);
    cudaGetSymbolAddress(&p_s,   g_s);
    cudaGetSymbolAddress(&p_t1,  g_t1);
    cudaGetSymbolAddress(&p_xc,  g_xc);
    cudaGetSymbolAddress(&p_invcnt, g_invcnt);
    float* xh  = (float*)p_xh;
    float* tx1 = (float*)p_tx1;
    float* s   = (float*)p_s;
    float* t1  = (float*)p_t1;
    float* xc  = (float*)p_xc;
    float* invcnt = (float*)p_invcnt;

    // graph prep (graph is launch input; recompute every call)
    prep_zero_kernel<<<(NN + 255)/256, 256>>>();
    prep_edge_kernel<<<(NE + 255)/256, 256>>>(ei, w);
    prep_node_kernel<<<(NN + 255)/256, 256>>>();

    // cell 1: 512 -> 128, output into xc
    run_cell(x,  ei, w, pre_w1, pre_b1, cw0_1, cw1_1, cb_1, sw_1, sb_1, lw_1, lb_1,
             xh, tx1, s, t1, xc, invcnt, FIN);
    // cell 2: 128 -> 128, xc -> xc (xc only read in step 1, rewritten in step 7)
    run_cell(xc, ei, w, pre_w2, pre_b2, cw0_2, cw1_2, cb_2, sw_2, sb_2, lw_2, lb_2,
             xh, tx1, s, t1, xc, invcnt, HH);

    // classifier: logits into d_out, then in-place log_softmax
    gemm_kernel<F_BIAS><<<dim3((NN+63)/64, 1), 256>>>(xc, cls_w, cls_b, out, nullptr, HH, CO);
    logsoftmax_kernel<<<(NN*32 + 255)/256, 256>>>(out);
}